// round 3
// baseline (speedup 1.0000x reference)
#include <cuda_runtime.h>
#include <cuda_bf16.h>

// Problem constants
#define BDIM 128   // batch (both sat and grd)
#define HDIM 4
#define WDIM 64
#define CDIM 16
#define FEAT (HDIM*WDIM*CDIM)   // 4096 floats per image

// Output layout (floats): [sat 524288][grd 524288][distance 16384 (g,s)][orien 16384 (s,g)]
#define OFF_SAT   0
#define OFF_GRD   (BDIM*FEAT)                 // 524288
#define OFF_DIST  (2*BDIM*FEAT)               // 1048576
#define OFF_OR    (2*BDIM*FEAT + BDIM*BDIM)   // 1064960

// SMEM layout
constexpr int G_PAD      = 132;                 // padded g-stride (conflict-free STS.128 transpose)
constexpr int SAT_STRIDE = 128;                 // w' dimension padded (need 127)
constexpr int SAT_FLOATS = HDIM*CDIM*SAT_STRIDE;       // 8192
constexpr int GRD_FLOATS = CDIM*16*G_PAD;              // 33792 (16 c x 16 kw x 132 g)
constexpr int SMEM_BYTES = (SAT_FLOATS + GRD_FLOATS)*4; // 167936 B

// One block per sat image s. 256 threads.
//   tx = t & 15  -> owns j = tx*4 .. tx*4+3   (64 shifts total)
//   ty = t >> 4  -> owns g = ty*8 .. ty*8+7   (128 grd total)
// 32 fp32 accumulators per thread. K loop: h(4) x kw-chunk(4 of 16) x c(16) x kw(16).
__global__ __launch_bounds__(256, 1)
void corr_argmax_kernel(const float* __restrict__ sat,
                        const float* __restrict__ grd,
                        float* __restrict__ dist,
                        float* __restrict__ orien)
{
    extern __shared__ float smem[];
    float* sat_s = smem;               // [h][c][SAT_STRIDE], w' in 0..126 (circular ext.)
    float* grd_s = smem + SAT_FLOATS;  // [c][kw'16][G_PAD], g in 0..127

    const int s  = blockIdx.x;
    const int t  = threadIdx.x;
    const int tx = t & 15;
    const int ty = t >> 4;
    const int tx4 = tx * 4;
    const int g0  = ty * 8;

    __shared__ float s_warp[8];
    __shared__ float s_norm;

    // ---- Stage sat[s] into smem as [h][c][w'] with circular extension w'=0..126 ----
    const float* satb = sat + s * FEAT;
    for (int i = t; i < FEAT/4; i += 256) {       // 1024 float4 loads, fully coalesced
        int c4 = i & 3;
        int w  = (i >> 2) & 63;
        int h  = i >> 8;
        float4 v = __ldg((const float4*)(satb + h*WDIM*CDIM + w*CDIM + c4*4));
        float vv[4] = {v.x, v.y, v.z, v.w};
        #pragma unroll
        for (int j = 0; j < 4; ++j) {
            int c = c4*4 + j;
            sat_s[(h*CDIM + c)*SAT_STRIDE + w] = vv[j];
            if (w < WDIM-1) sat_s[(h*CDIM + c)*SAT_STRIDE + w + WDIM] = vv[j];
        }
    }
    __syncthreads();

    // ---- ||sat[s]|| (shift-invariant, replaces the per-(s,g) crop norm) ----
    {
        float ss = 0.f;
        for (int i = t; i < FEAT; i += 256) {
            float v = sat_s[(i >> 6)*SAT_STRIDE + (i & 63)];
            ss += v * v;
        }
        #pragma unroll
        for (int o = 16; o > 0; o >>= 1) ss += __shfl_down_sync(0xffffffffu, ss, o);
        if ((t & 31) == 0) s_warp[t >> 5] = ss;
        __syncthreads();
        if (t == 0) {
            float tot = 0.f;
            #pragma unroll
            for (int i = 0; i < 8; ++i) tot += s_warp[i];
            s_norm = fmaxf(sqrtf(tot), 1e-12f);
        }
    }

    float acc[4][8];
    #pragma unroll
    for (int r = 0; r < 4; ++r)
        #pragma unroll
        for (int u = 0; u < 8; ++u) acc[r][u] = 0.f;

    // ---- Main K loop ----
    for (int h = 0; h < HDIM; ++h) {
        for (int kq = 0; kq < 4; ++kq) {
            __syncthreads();   // protect grd_s reuse across chunks
            // Stage grd chunk (h, kw = kq*16..kq*16+15), all 128 g, all 16 c.
            // Coalesced LDG.128, in-register 4x4 transpose, conflict-free STS.128.
            #pragma unroll
            for (int it = 0; it < 8; ++it) {
                int flat = it*256 + t;        // 0..2047
                int g4   = flat >> 6;         // 0..31 -> g = g4*4 + gg
                int q    = flat & 63;         // contiguous 16B units within one g row
                int kwp  = q >> 2;            // 0..15
                int c4   = q & 3;             // c group of 4
                const float* gp = grd + (g4*4)*FEAT + h*(WDIM*CDIM) + (kq*16 + kwp)*CDIM + c4*4;
                float a[4][4];
                *(float4*)a[0] = __ldg((const float4*)(gp));
                *(float4*)a[1] = __ldg((const float4*)(gp +   FEAT));
                *(float4*)a[2] = __ldg((const float4*)(gp + 2*FEAT));
                *(float4*)a[3] = __ldg((const float4*)(gp + 3*FEAT));
                #pragma unroll
                for (int j = 0; j < 4; ++j) {
                    int c = c4*4 + j;
                    float4 w4 = make_float4(a[0][j], a[1][j], a[2][j], a[3][j]);
                    *(float4*)&grd_s[(c*16 + kwp)*G_PAD + g4*4] = w4;
                }
            }
            __syncthreads();

            const int kwbase = kq*16;
            for (int c = 0; c < CDIM; ++c) {          // kept rolled: limits I$ footprint
                const float* srow = &sat_s[(h*CDIM + c)*SAT_STRIDE + tx4 + kwbase];
                const float* grow = &grd_s[(c*16)*G_PAD + g0];
                float a0 = srow[0], a1 = srow[1], a2 = srow[2];
                #pragma unroll
                for (int kw = 0; kw < 16; ++kw) {
                    float a3 = srow[kw + 3];          // sliding register window: 1 LDS/step
                    float4 b0 = *(const float4*)&grow[kw*G_PAD];
                    float4 b1 = *(const float4*)&grow[kw*G_PAD + 4];
                    float bb[8] = {b0.x,b0.y,b0.z,b0.w,b1.x,b1.y,b1.z,b1.w};
                    #pragma unroll
                    for (int u = 0; u < 8; ++u) {
                        acc[0][u] = fmaf(a0, bb[u], acc[0][u]);
                        acc[1][u] = fmaf(a1, bb[u], acc[1][u]);
                        acc[2][u] = fmaf(a2, bb[u], acc[2][u]);
                        acc[3][u] = fmaf(a3, bb[u], acc[3][u]);
                    }
                    a0 = a1; a1 = a2; a2 = a3;
                }
            }
        }
    }
    __syncthreads();

    // ---- argmax over j (first-max tie-break, matching jnp.argmax) ----
    float* redv = grd_s;                 // reuse staged area: 128*16 floats
    int*   redj = (int*)(grd_s + 2048);  // 128*16 ints
    #pragma unroll
    for (int u = 0; u < 8; ++u) {
        int g = g0 + u;
        float bv = acc[0][u]; int bj = tx4;
        #pragma unroll
        for (int r = 1; r < 4; ++r)
            if (acc[r][u] > bv) { bv = acc[r][u]; bj = tx4 + r; }   // strict > keeps earliest j
        redv[g*16 + tx] = bv;
        redj[g*16 + tx] = bj;
    }
    __syncthreads();
    if (t < 128) {
        int g = t;
        float bv = redv[g*16]; int bj = redj[g*16];
        #pragma unroll
        for (int i = 1; i < 16; ++i) {               // ascending tx == ascending j
            float v = redv[g*16 + i];
            if (v > bv) { bv = v; bj = redj[g*16 + i]; }
        }
        orien[s*BDIM + g] = (float)bj;
        dist[g*BDIM + s]  = 2.0f - 2.0f * (bv / s_norm);
    }
}

extern "C" void kernel_launch(void* const* d_in, const int* in_sizes, int n_in,
                              void* d_out, int out_size)
{
    const float* sat = (const float*)d_in[0];
    const float* grd = (const float*)d_in[1];
    float* out = (float*)d_out;

    // Echo inputs into the output tuple slots (async D2D, graph-capturable).
    cudaMemcpyAsync(out + OFF_SAT, sat, (size_t)BDIM*FEAT*sizeof(float), cudaMemcpyDeviceToDevice);
    cudaMemcpyAsync(out + OFF_GRD, grd, (size_t)BDIM*FEAT*sizeof(float), cudaMemcpyDeviceToDevice);

    cudaFuncSetAttribute(corr_argmax_kernel,
                         cudaFuncAttributeMaxDynamicSharedMemorySize, SMEM_BYTES);
    corr_argmax_kernel<<<BDIM, 256, SMEM_BYTES>>>(sat, grd, out + OFF_DIST, out + OFF_OR);
}

// round 4
// speedup vs baseline: 1.1541x; 1.1541x over previous
#include <cuda_runtime.h>
#include <cuda_bf16.h>
#include <cstdint>

// Problem constants
#define BDIM 128   // batch (both sat and grd)
#define HDIM 4
#define WDIM 64
#define CDIM 16
#define FEAT (HDIM*WDIM*CDIM)   // 4096 floats per image

// Output layout (floats): [sat 524288][grd 524288][distance 16384 (g,s)][orien 16384 (s,g)]
#define OFF_SAT   0
#define OFF_GRD   (BDIM*FEAT)                 // 524288
#define OFF_DIST  (2*BDIM*FEAT)               // 1048576
#define OFF_OR    (2*BDIM*FEAT + BDIM*BDIM)   // 1064960

// SMEM layout
constexpr int G_PAD      = 132;                 // padded g-stride (16B-aligned rows: 132*4=528)
constexpr int SAT_STRIDE = 128;                 // w' dimension padded (need 127)
constexpr int SAT_FLOATS = HDIM*CDIM*SAT_STRIDE;        // 8192
constexpr int GRD_FLOATS = CDIM*16*G_PAD;               // 33792 (16 c x 16 kw x 132 g)
constexpr int SMEM_BYTES = (SAT_FLOATS + GRD_FLOATS)*4; // 167936 B

// fma.rn.f32x2 — packed 2-wide fp32 FMA (Blackwell). ptxas never auto-fuses this;
// inline PTX is the only route. Exact fp32 per lane.
__device__ __forceinline__ void ffma2(unsigned long long& acc,
                                      unsigned long long a,
                                      unsigned long long b)
{
    asm("fma.rn.f32x2 %0, %1, %2, %0;" : "+l"(acc) : "l"(a), "l"(b));
}
__device__ __forceinline__ unsigned long long pack2(float v)
{
    unsigned long long r;
    unsigned u = __float_as_uint(v);
    asm("mov.b64 %0, {%1, %1};" : "=l"(r) : "r"(u));
    return r;
}

// One block per sat image s. 256 threads.
//   warp w = t>>5 -> owns j = w*8 .. w*8+7   (64 shifts total)
//   lane l = t&31 -> owns g = l*4 .. l*4+3   (128 grd total)
// 32 fp32 accumulators per thread, held as 16 packed f32x2.
__global__ __launch_bounds__(256, 1)
void corr_argmax_kernel(const float* __restrict__ sat,
                        const float* __restrict__ grd,
                        float* __restrict__ dist,
                        float* __restrict__ orien)
{
    extern __shared__ float smem[];
    float* sat_s = smem;               // [h][c][SAT_STRIDE], w' in 0..126 (circular ext.)
    float* grd_s = smem + SAT_FLOATS;  // [c][kw'16][G_PAD], g in 0..127

    const int s  = blockIdx.x;
    const int t  = threadIdx.x;
    const int w  = t >> 5;             // warp id: j group
    const int l  = t & 31;             // lane id: g group
    const int j0 = w * 8;
    const int g0 = l * 4;

    __shared__ float s_warp[8];
    __shared__ float s_norm;

    // ---- Stage sat[s] into smem as [h][c][w'] with circular extension w'=0..126 ----
    const float* satb = sat + s * FEAT;
    for (int i = t; i < FEAT/4; i += 256) {       // 1024 float4 loads, fully coalesced
        int c4 = i & 3;
        int wI = (i >> 2) & 63;
        int h  = i >> 8;
        float4 v = __ldg((const float4*)(satb + h*WDIM*CDIM + wI*CDIM + c4*4));
        float vv[4] = {v.x, v.y, v.z, v.w};
        #pragma unroll
        for (int j = 0; j < 4; ++j) {
            int c = c4*4 + j;
            sat_s[(h*CDIM + c)*SAT_STRIDE + wI] = vv[j];
            if (wI < WDIM-1) sat_s[(h*CDIM + c)*SAT_STRIDE + wI + WDIM] = vv[j];
        }
    }
    __syncthreads();

    // ---- ||sat[s]|| (shift-invariant; replaces the per-(s,g) crop norm) ----
    {
        float ss = 0.f;
        for (int i = t; i < FEAT; i += 256) {
            float v = sat_s[(i >> 6)*SAT_STRIDE + (i & 63)];
            ss += v * v;
        }
        #pragma unroll
        for (int o = 16; o > 0; o >>= 1) ss += __shfl_down_sync(0xffffffffu, ss, o);
        if (l == 0) s_warp[w] = ss;
        __syncthreads();
        if (t == 0) {
            float tot = 0.f;
            #pragma unroll
            for (int i = 0; i < 8; ++i) tot += s_warp[i];
            s_norm = fmaxf(sqrtf(tot), 1e-12f);
        }
    }

    // acc2[jj][p]: packed pair (g0+2p, g0+2p+1) for shift j0+jj
    unsigned long long acc2[8][2];
    #pragma unroll
    for (int jj = 0; jj < 8; ++jj) { acc2[jj][0] = 0ull; acc2[jj][1] = 0ull; }

    // ---- Main K loop: h(4) x kw-chunk(4 of 16) x c(16) x kw(16) ----
    for (int h = 0; h < HDIM; ++h) {
        for (int kq = 0; kq < 4; ++kq) {
            __syncthreads();   // protect grd_s reuse across chunks
            // Stage grd chunk (h, kw = kq*16..kq*16+15), all 128 g, all 16 c.
            // Coalesced LDG.128, in-register 4x4 transpose, STS.128.
            #pragma unroll
            for (int it = 0; it < 8; ++it) {
                int flat = it*256 + t;        // 0..2047
                int g4   = flat >> 6;         // 0..31 -> g = g4*4 + gg
                int q    = flat & 63;
                int kwp  = q >> 2;            // 0..15
                int c4   = q & 3;             // c group of 4
                const float* gp = grd + (g4*4)*FEAT + h*(WDIM*CDIM) + (kq*16 + kwp)*CDIM + c4*4;
                float a[4][4];
                *(float4*)a[0] = __ldg((const float4*)(gp));
                *(float4*)a[1] = __ldg((const float4*)(gp +   FEAT));
                *(float4*)a[2] = __ldg((const float4*)(gp + 2*FEAT));
                *(float4*)a[3] = __ldg((const float4*)(gp + 3*FEAT));
                #pragma unroll
                for (int j = 0; j < 4; ++j) {
                    int c = c4*4 + j;
                    float4 w4 = make_float4(a[0][j], a[1][j], a[2][j], a[3][j]);
                    *(float4*)&grd_s[(c*16 + kwp)*G_PAD + g4*4] = w4;
                }
            }
            __syncthreads();

            const int kwbase = kq*16;
            for (int c = 0; c < CDIM; ++c) {          // kept rolled: limits I$ footprint
                const float* srow = &sat_s[(h*CDIM + c)*SAT_STRIDE + j0 + kwbase];
                const float* grow = &grd_s[(c*16)*G_PAD + g0];
                // Preload+pack the 23 sat values this warp needs (broadcast LDS, packed once)
                unsigned long long ap[23];
                #pragma unroll
                for (int i = 0; i < 23; ++i) ap[i] = pack2(srow[i]);
                #pragma unroll
                for (int kw = 0; kw < 16; ++kw) {
                    // one LDS.128: lands as two ready-to-use f32x2 operand pairs
                    double2 b = *(const double2*)&grow[kw*G_PAD];
                    unsigned long long b0 = __double_as_longlong(b.x);
                    unsigned long long b1 = __double_as_longlong(b.y);
                    #pragma unroll
                    for (int jj = 0; jj < 8; ++jj) {
                        ffma2(acc2[jj][0], ap[kw + jj], b0);
                        ffma2(acc2[jj][1], ap[kw + jj], b1);
                    }
                }
            }
        }
    }
    __syncthreads();

    // ---- argmax over j (first-max tie-break, matching jnp.argmax) ----
    // Per thread: best over its 8 j for each of its 4 g, then reduce over 8 warps.
    float* redv = grd_s;                 // reuse staged area: 128 g x 8 w
    int*   redj = (int*)(grd_s + 1024);
    #pragma unroll
    for (int gg = 0; gg < 4; ++gg) {
        int p = gg >> 1;                 // which packed acc
        int hi = gg & 1;                 // lo/hi half
        float bv; int bj = j0;
        {
            unsigned long long a0 = acc2[0][p];
            unsigned u = hi ? (unsigned)(a0 >> 32) : (unsigned)(a0 & 0xffffffffull);
            bv = __uint_as_float(u);
        }
        #pragma unroll
        for (int jj = 1; jj < 8; ++jj) {
            unsigned long long aj = acc2[jj][p];
            unsigned u = hi ? (unsigned)(aj >> 32) : (unsigned)(aj & 0xffffffffull);
            float v = __uint_as_float(u);
            if (v > bv) { bv = v; bj = j0 + jj; }   // strict > keeps earliest j
        }
        int g = g0 + gg;
        redv[g*8 + w] = bv;
        redj[g*8 + w] = bj;
    }
    __syncthreads();
    if (t < 128) {
        int g = t;
        float bv = redv[g*8]; int bj = redj[g*8];
        #pragma unroll
        for (int i = 1; i < 8; ++i) {                // ascending warp == ascending j
            float v = redv[g*8 + i];
            if (v > bv) { bv = v; bj = redj[g*8 + i]; }
        }
        orien[s*BDIM + g] = (float)bj;
        dist[g*BDIM + s]  = 2.0f - 2.0f * (bv / s_norm);
    }
}

extern "C" void kernel_launch(void* const* d_in, const int* in_sizes, int n_in,
                              void* d_out, int out_size)
{
    const float* sat = (const float*)d_in[0];
    const float* grd = (const float*)d_in[1];
    float* out = (float*)d_out;

    // Echo inputs into the output tuple slots (async D2D, graph-capturable).
    cudaMemcpyAsync(out + OFF_SAT, sat, (size_t)BDIM*FEAT*sizeof(float), cudaMemcpyDeviceToDevice);
    cudaMemcpyAsync(out + OFF_GRD, grd, (size_t)BDIM*FEAT*sizeof(float), cudaMemcpyDeviceToDevice);

    cudaFuncSetAttribute(corr_argmax_kernel,
                         cudaFuncAttributeMaxDynamicSharedMemorySize, SMEM_BYTES);
    corr_argmax_kernel<<<BDIM, 256, SMEM_BYTES>>>(sat, grd, out + OFF_DIST, out + OFF_OR);
}

// round 5
// speedup vs baseline: 1.1766x; 1.0195x over previous
#include <cuda_runtime.h>
#include <cuda_bf16.h>
#include <cstdint>

// Problem constants
#define BDIM 128   // batch (both sat and grd)
#define HDIM 4
#define WDIM 64
#define CDIM 16
#define FEAT (HDIM*WDIM*CDIM)   // 4096 floats per image

// Output layout (floats): [sat 524288][grd 524288][distance 16384 (g,s)][orien 16384 (s,g)]
#define OFF_SAT   0
#define OFF_GRD   (BDIM*FEAT)                 // 524288
#define OFF_DIST  (2*BDIM*FEAT)               // 1048576
#define OFF_OR    (2*BDIM*FEAT + BDIM*BDIM)   // 1064960

#define NTHREADS 512

// SMEM layout
constexpr int G_PAD      = 132;                 // padded g-stride (16B-aligned rows)
constexpr int SAT_STRIDE = 128;                 // w' dimension padded (need 127)
constexpr int SAT_FLOATS = HDIM*CDIM*SAT_STRIDE;        // 8192
constexpr int GRD_FLOATS = CDIM*16*G_PAD;               // 33792 (16 c x 16 kw x 132 g)
constexpr int SMEM_BYTES = (SAT_FLOATS + GRD_FLOATS)*4; // 167936 B

// fma.rn.f32x2 — packed 2-wide fp32 FMA (Blackwell). ptxas never auto-fuses this;
// inline PTX is the only route. Exact fp32 per lane.
__device__ __forceinline__ void ffma2(unsigned long long& acc,
                                      unsigned long long a,
                                      unsigned long long b)
{
    asm("fma.rn.f32x2 %0, %1, %2, %0;" : "+l"(acc) : "l"(a), "l"(b));
}
__device__ __forceinline__ unsigned long long pack2(float v)
{
    unsigned long long r;
    unsigned u = __float_as_uint(v);
    asm("mov.b64 %0, {%1, %1};" : "=l"(r) : "r"(u));
    return r;
}

// One block per sat image s. 512 threads = 16 warps (4 per SMSP for latency hiding).
//   wj = (t>>5)&7 -> owns j = wj*8 .. wj*8+7     (64 shifts over 8 j-groups)
//   gh = t>>8     -> g half (0 or 1)
//   lane l        -> owns g = gh*64 + l*2, l*2+1 (one packed f32x2 per b load)
// 16 fp32 accumulators per thread, held as 8 packed f32x2.
__global__ __launch_bounds__(NTHREADS, 1)
void corr_argmax_kernel(const float* __restrict__ sat,
                        const float* __restrict__ grd,
                        float* __restrict__ dist,
                        float* __restrict__ orien)
{
    extern __shared__ float smem[];
    float* sat_s = smem;               // [h][c][SAT_STRIDE], w' in 0..126 (circular ext.)
    float* grd_s = smem + SAT_FLOATS;  // [c][kw'16][G_PAD], g in 0..127

    const int s  = blockIdx.x;
    const int t  = threadIdx.x;
    const int w  = t >> 5;             // warp id 0..15
    const int l  = t & 31;
    const int wj = w & 7;              // j group
    const int gh = w >> 3;             // g half
    const int j0 = wj * 8;
    const int g0 = gh * 64 + l * 2;

    __shared__ float s_warp[16];
    __shared__ float s_norm;

    // ---- Stage sat[s] into smem as [h][c][w'] with circular extension w'=0..126 ----
    const float* satb = sat + s * FEAT;
    for (int i = t; i < FEAT/4; i += NTHREADS) {    // 1024 float4 loads, coalesced
        int c4 = i & 3;
        int wI = (i >> 2) & 63;
        int h  = i >> 8;
        float4 v = __ldg((const float4*)(satb + h*WDIM*CDIM + wI*CDIM + c4*4));
        float vv[4] = {v.x, v.y, v.z, v.w};
        #pragma unroll
        for (int j = 0; j < 4; ++j) {
            int c = c4*4 + j;
            sat_s[(h*CDIM + c)*SAT_STRIDE + wI] = vv[j];
            if (wI < WDIM-1) sat_s[(h*CDIM + c)*SAT_STRIDE + wI + WDIM] = vv[j];
        }
    }
    __syncthreads();

    // ---- ||sat[s]|| (shift-invariant; replaces the per-(s,g) crop norm) ----
    {
        float ss = 0.f;
        for (int i = t; i < FEAT; i += NTHREADS) {
            float v = sat_s[(i >> 6)*SAT_STRIDE + (i & 63)];
            ss += v * v;
        }
        #pragma unroll
        for (int o = 16; o > 0; o >>= 1) ss += __shfl_down_sync(0xffffffffu, ss, o);
        if (l == 0) s_warp[w] = ss;
        __syncthreads();
        if (t == 0) {
            float tot = 0.f;
            #pragma unroll
            for (int i = 0; i < 16; ++i) tot += s_warp[i];
            s_norm = fmaxf(sqrtf(tot), 1e-12f);
        }
    }

    // acc2[jj]: packed pair (g0, g0+1) for shift j0+jj
    unsigned long long acc2[8];
    #pragma unroll
    for (int jj = 0; jj < 8; ++jj) acc2[jj] = 0ull;

    // ---- Main K loop: h(4) x kw-chunk(4 of 16) x c(16) x kw(16) ----
    for (int h = 0; h < HDIM; ++h) {
        for (int kq = 0; kq < 4; ++kq) {
            __syncthreads();   // protect grd_s reuse across chunks
            // Stage grd chunk (h, kw = kq*16..kq*16+15), all 128 g, all 16 c.
            // Coalesced LDG.128, in-register 4x4 transpose, STS.128.
            #pragma unroll
            for (int it = 0; it < 4; ++it) {
                int flat = it*NTHREADS + t;   // 0..2047
                int g4   = flat >> 6;         // 0..31 -> g = g4*4 + gg
                int q    = flat & 63;
                int kwp  = q >> 2;            // 0..15
                int c4   = q & 3;             // c group of 4
                const float* gp = grd + (g4*4)*FEAT + h*(WDIM*CDIM) + (kq*16 + kwp)*CDIM + c4*4;
                float a[4][4];
                *(float4*)a[0] = __ldg((const float4*)(gp));
                *(float4*)a[1] = __ldg((const float4*)(gp +   FEAT));
                *(float4*)a[2] = __ldg((const float4*)(gp + 2*FEAT));
                *(float4*)a[3] = __ldg((const float4*)(gp + 3*FEAT));
                #pragma unroll
                for (int j = 0; j < 4; ++j) {
                    int c = c4*4 + j;
                    float4 w4 = make_float4(a[0][j], a[1][j], a[2][j], a[3][j]);
                    *(float4*)&grd_s[(c*16 + kwp)*G_PAD + g4*4] = w4;
                }
            }
            __syncthreads();

            const int kwbase = kq*16;
            for (int c = 0; c < CDIM; ++c) {          // kept rolled: limits I$ footprint
                const float* srow = &sat_s[(h*CDIM + c)*SAT_STRIDE + j0 + kwbase];
                const float* grow = &grd_s[(c*16)*G_PAD + g0];
                // Two kw half-passes of 8: 15-wide packed a-window each (register-friendly)
                #pragma unroll
                for (int half = 0; half < 2; ++half) {
                    const int kwo = half * 8;
                    unsigned long long ap[15];
                    #pragma unroll
                    for (int i = 0; i < 15; ++i) ap[i] = pack2(srow[kwo + i]);
                    #pragma unroll
                    for (int kw = 0; kw < 8; ++kw) {
                        // one LDS.64: lands as a ready-to-use f32x2 operand pair
                        unsigned long long b =
                            __double_as_longlong(*(const double*)&grow[(kwo + kw)*G_PAD]);
                        #pragma unroll
                        for (int jj = 0; jj < 8; ++jj)
                            ffma2(acc2[jj], ap[kw + jj], b);
                    }
                }
            }
        }
    }
    __syncthreads();

    // ---- argmax over j (first-max tie-break, matching jnp.argmax) ----
    // Per thread: best over its 8 j for each of its 2 g, then reduce over 8 j-groups.
    float* redv = grd_s;                 // reuse staged area: 128 g x 8 jgroups
    int*   redj = (int*)(grd_s + 1024);
    #pragma unroll
    for (int gg = 0; gg < 2; ++gg) {
        float bv; int bj = j0;
        {
            unsigned u = gg ? (unsigned)(acc2[0] >> 32) : (unsigned)(acc2[0] & 0xffffffffull);
            bv = __uint_as_float(u);
        }
        #pragma unroll
        for (int jj = 1; jj < 8; ++jj) {
            unsigned u = gg ? (unsigned)(acc2[jj] >> 32) : (unsigned)(acc2[jj] & 0xffffffffull);
            float v = __uint_as_float(u);
            if (v > bv) { bv = v; bj = j0 + jj; }   // strict > keeps earliest j
        }
        int g = g0 + gg;
        redv[g*8 + wj] = bv;
        redj[g*8 + wj] = bj;
    }
    __syncthreads();
    if (t < 128) {
        int g = t;
        float bv = redv[g*8]; int bj = redj[g*8];
        #pragma unroll
        for (int i = 1; i < 8; ++i) {                // ascending jgroup == ascending j
            float v = redv[g*8 + i];
            if (v > bv) { bv = v; bj = redj[g*8 + i]; }
        }
        orien[s*BDIM + g] = (float)bj;
        dist[g*BDIM + s]  = 2.0f - 2.0f * (bv / s_norm);
    }
}

extern "C" void kernel_launch(void* const* d_in, const int* in_sizes, int n_in,
                              void* d_out, int out_size)
{
    const float* sat = (const float*)d_in[0];
    const float* grd = (const float*)d_in[1];
    float* out = (float*)d_out;

    // Echo inputs into the output tuple slots (async D2D, graph-capturable).
    cudaMemcpyAsync(out + OFF_SAT, sat, (size_t)BDIM*FEAT*sizeof(float), cudaMemcpyDeviceToDevice);
    cudaMemcpyAsync(out + OFF_GRD, grd, (size_t)BDIM*FEAT*sizeof(float), cudaMemcpyDeviceToDevice);

    cudaFuncSetAttribute(corr_argmax_kernel,
                         cudaFuncAttributeMaxDynamicSharedMemorySize, SMEM_BYTES);
    corr_argmax_kernel<<<BDIM, NTHREADS, SMEM_BYTES>>>(sat, grd, out + OFF_DIST, out + OFF_OR);
}